// round 2
// baseline (speedup 1.0000x reference)
#include <cuda_runtime.h>
#include <cuda_bf16.h>
#include <math.h>

// ---------------------------------------------------------------------------
// Problem constants
// ---------------------------------------------------------------------------
#define BB   16
#define CC   256
#define HH   56
#define WW   56
#define HW   (HH*WW)          // 3136
#define KK   7
#define GCC  16
#define GG   16               // groups
#define RED  64
#define KKG  (KK*KK*GG)       // 784
#define PADI 3

// ---------------------------------------------------------------------------
// Scratch (device globals; no allocation allowed)
// ---------------------------------------------------------------------------
__device__ float g_y [BB*CC*HW];     // 51.4 MB  tanh(bn1(conv1))
__device__ float g_r [BB*RED*HW];    // 12.8 MB  relu(bn_red(red conv))
__device__ float g_wd[BB*KKG*HW];    // 157 MB   span conv output (dyn kernels)
__device__ float g_z [BB*CC*HW];     // 51.4 MB  tanh(bn2(involution))

__device__ float g_s1[CC], g_h1[CC];
__device__ float g_sr[RED], g_hr[RED];
__device__ float g_s2[CC], g_h2[CC];
__device__ float g_s3[CC], g_h3[CC];

// ---------------------------------------------------------------------------
// Fold BN (+conv bias) into per-channel scale/shift
// ---------------------------------------------------------------------------
__global__ void precompute_kernel(
    const float* __restrict__ b1,
    const float* __restrict__ g1, const float* __restrict__ be1,
    const float* __restrict__ m1, const float* __restrict__ v1,
    const float* __restrict__ redb,
    const float* __restrict__ rg, const float* __restrict__ rb,
    const float* __restrict__ rm, const float* __restrict__ rv,
    const float* __restrict__ g2, const float* __restrict__ be2,
    const float* __restrict__ m2, const float* __restrict__ v2,
    const float* __restrict__ b3,
    const float* __restrict__ g3, const float* __restrict__ be3,
    const float* __restrict__ m3, const float* __restrict__ v3)
{
    int c = threadIdx.x;
    if (c < CC) {
        float s = g1[c] * rsqrtf(v1[c] + 1e-5f);
        g_s1[c] = s; g_h1[c] = b1[c]*s + be1[c] - m1[c]*s;
        s = g2[c] * rsqrtf(v2[c] + 1e-5f);
        g_s2[c] = s; g_h2[c] = be2[c] - m2[c]*s;          // no conv bias here
        s = g3[c] * rsqrtf(v3[c] + 1e-5f);
        g_s3[c] = s; g_h3[c] = b3[c]*s + be3[c] - m3[c]*s;
    }
    if (c < RED) {
        float s = rg[c] * rsqrtf(rv[c] + 1e-5f);
        g_sr[c] = s; g_hr[c] = redb[c]*s + rb[c] - rm[c]*s;
    }
}

// ---------------------------------------------------------------------------
// Tiled SGEMM:  C[b][m][n] = sum_k A[m][k] * B[b][k][n], fused epilogues.
//   EPI 0: tanh(v*scale+shift)    EPI 1: relu(v*scale+shift)
//   EPI 2: v+shift                EPI 3: v*scale+shift + resid
// Block tile 64x128, K-tile 16, 256 threads, each 4x8 outputs.
// ---------------------------------------------------------------------------
#define BM 64
#define BN 128
#define BKT 16
#define TM 4
#define TN 8

template<int EPI>
__global__ __launch_bounds__(256)
void gemm_epi(const float* __restrict__ A, const float* __restrict__ Bm,
              float* __restrict__ Cm,
              const float* __restrict__ scale, const float* __restrict__ shift,
              const float* __restrict__ resid,
              int M, int N, int K, long strideB, long strideC, long strideR)
{
    const int b  = blockIdx.z;
    const float* Bp = Bm + (long)b * strideB;
    float*       Cp = Cm + (long)b * strideC;
    const float* Rp = (EPI == 3) ? resid + (long)b * strideR : nullptr;

    const int m0 = blockIdx.y * BM;
    const int n0 = blockIdx.x * BN;
    const int tid = threadIdx.x;
    const int ty = tid >> 4;        // 0..15
    const int tx = tid & 15;        // 0..15

    __shared__ float As[BKT][BM];
    __shared__ float Bs[BKT][BN];

    float acc[TM][TN];
    #pragma unroll
    for (int i = 0; i < TM; i++)
        #pragma unroll
        for (int j = 0; j < TN; j++) acc[i][j] = 0.f;

    for (int kt = 0; kt < K; kt += BKT) {
        // --- load A tile (BM x BKT): 256 float4 loads, one per thread ---
        {
            int row = tid >> 2;           // 0..63
            int kc  = (tid & 3) << 2;     // 0,4,8,12
            float4 v = make_float4(0.f, 0.f, 0.f, 0.f);
            int gm = m0 + row;
            if (gm < M)
                v = *reinterpret_cast<const float4*>(&A[(long)gm * K + kt + kc]);
            As[kc + 0][row] = v.x;
            As[kc + 1][row] = v.y;
            As[kc + 2][row] = v.z;
            As[kc + 3][row] = v.w;
        }
        // --- load B tile (BKT x BN): 512 float4 slots, 2 per thread ---
        #pragma unroll
        for (int p = 0; p < 2; p++) {
            int idx = p * 256 + tid;      // 0..511
            int k   = idx >> 5;           // 0..15
            int n4  = (idx & 31) << 2;    // 0..124
            float4 v = make_float4(0.f, 0.f, 0.f, 0.f);
            int gn = n0 + n4;
            if (gn < N)   // N % 4 == 0, n4 % 4 == 0 -> whole float4 valid
                v = *reinterpret_cast<const float4*>(&Bp[(long)(kt + k) * N + gn]);
            *reinterpret_cast<float4*>(&Bs[k][n4]) = v;
        }
        __syncthreads();

        #pragma unroll
        for (int k = 0; k < BKT; k++) {
            float4 av = *reinterpret_cast<const float4*>(&As[k][ty * TM]);
            float4 b0 = *reinterpret_cast<const float4*>(&Bs[k][tx * TN]);
            float4 b1 = *reinterpret_cast<const float4*>(&Bs[k][tx * TN + 4]);
            float a[TM] = {av.x, av.y, av.z, av.w};
            float bv[TN] = {b0.x, b0.y, b0.z, b0.w, b1.x, b1.y, b1.z, b1.w};
            #pragma unroll
            for (int i = 0; i < TM; i++)
                #pragma unroll
                for (int j = 0; j < TN; j++)
                    acc[i][j] = fmaf(a[i], bv[j], acc[i][j]);
        }
        __syncthreads();
    }

    // --- epilogue ---
    #pragma unroll
    for (int i = 0; i < TM; i++) {
        int gm = m0 + ty * TM + i;
        if (gm >= M) continue;
        float sc = 1.f, sh;
        if (EPI == 2) { sh = shift[gm]; }
        else          { sc = scale[gm]; sh = shift[gm]; }
        #pragma unroll
        for (int j = 0; j < TN; j++) {
            int gn = n0 + tx * TN + j;
            if (gn >= N) continue;
            float v = acc[i][j];
            if (EPI == 0)      v = tanhf(fmaf(v, sc, sh));
            else if (EPI == 1) v = fmaxf(fmaf(v, sc, sh), 0.f);
            else if (EPI == 2) v = v + sh;
            else               v = fmaf(v, sc, sh) + Rp[(long)gm * N + gn];
            Cp[(long)gm * N + gn] = v;
        }
    }
}

// ---------------------------------------------------------------------------
// Involution + bn2 + tanh, fused.
// Block: one (batch, group), spatial tile 28x8. 16 group-channels in regs.
// z[b, g*16+gc, h, w] = tanh(bn2( sum_ij wd[b,g*49+ij,h,w] * y_pad[...] ))
// ---------------------------------------------------------------------------
#define TW 28
#define TH 8

__global__ __launch_bounds__(224)
void involution_kernel()
{
    const int bg = blockIdx.z;
    const int b  = bg >> 4;
    const int g  = bg & 15;
    const int h0 = blockIdx.y * TH;
    const int w0 = blockIdx.x * TW;
    const int tid = threadIdx.y * TW + threadIdx.x;

    __shared__ float ys[GCC][TH + 6][TW + 6];   // 16 x 14 x 34 = 30.4 KB

    // cooperative haloed load of y for this group's 16 channels
    const float* ybase = g_y + ((long)(b * CC + g * GCC)) * HW;
    const int TOT = GCC * (TH + 6) * (TW + 6);  // 7616
    for (int idx = tid; idx < TOT; idx += TW * TH) {
        int gc  = idx / ((TH + 6) * (TW + 6));
        int rem = idx % ((TH + 6) * (TW + 6));
        int lh  = rem / (TW + 6);
        int lw  = rem % (TW + 6);
        int gh = h0 + lh - PADI;
        int gw = w0 + lw - PADI;
        float v = 0.f;
        if (gh >= 0 && gh < HH && gw >= 0 && gw < WW)
            v = ybase[(long)gc * HW + gh * WW + gw];
        ys[gc][lh][lw] = v;
    }
    __syncthreads();

    const int h = h0 + threadIdx.y;
    const int w = w0 + threadIdx.x;
    const float* wdp = g_wd + ((long)b * KKG + g * (KK * KK)) * HW + h * WW + w;

    float acc[GCC];
    #pragma unroll
    for (int gc = 0; gc < GCC; gc++) acc[gc] = 0.f;

    #pragma unroll
    for (int i = 0; i < KK; i++) {
        #pragma unroll
        for (int j = 0; j < KK; j++) {
            float wv = wdp[(long)(i * KK + j) * HW];
            #pragma unroll
            for (int gc = 0; gc < GCC; gc++)
                acc[gc] = fmaf(wv, ys[gc][threadIdx.y + i][threadIdx.x + j], acc[gc]);
        }
    }

    long zbase = ((long)(b * CC + g * GCC)) * HW + h * WW + w;
    #pragma unroll
    for (int gc = 0; gc < GCC; gc++) {
        int c = g * GCC + gc;
        g_z[zbase + (long)gc * HW] = tanhf(fmaf(acc[gc], g_s2[c], g_h2[c]));
    }
}

// ---------------------------------------------------------------------------
// Host
// ---------------------------------------------------------------------------
extern "C" void kernel_launch(void* const* d_in, const int* in_sizes, int n_in,
                              void* d_out, int out_size)
{
    const float* x     = (const float*)d_in[0];
    const float* w1    = (const float*)d_in[1];
    const float* b1    = (const float*)d_in[2];
    const float* bn1_g = (const float*)d_in[3];
    const float* bn1_b = (const float*)d_in[4];
    const float* bn1_m = (const float*)d_in[5];
    const float* bn1_v = (const float*)d_in[6];
    const float* red_w = (const float*)d_in[7];
    const float* red_b = (const float*)d_in[8];
    const float* rbn_g = (const float*)d_in[9];
    const float* rbn_b = (const float*)d_in[10];
    const float* rbn_m = (const float*)d_in[11];
    const float* rbn_v = (const float*)d_in[12];
    const float* span_w= (const float*)d_in[13];
    const float* span_b= (const float*)d_in[14];
    const float* bn2_g = (const float*)d_in[15];
    const float* bn2_b = (const float*)d_in[16];
    const float* bn2_m = (const float*)d_in[17];
    const float* bn2_v = (const float*)d_in[18];
    const float* w3    = (const float*)d_in[19];
    const float* b3    = (const float*)d_in[20];
    const float* bn3_g = (const float*)d_in[21];
    const float* bn3_b = (const float*)d_in[22];
    const float* bn3_m = (const float*)d_in[23];
    const float* bn3_v = (const float*)d_in[24];
    float* out = (float*)d_out;

    float *p_y, *p_r, *p_wd, *p_z;
    float *p_s1, *p_h1, *p_sr, *p_hr, *p_s3, *p_h3;
    cudaGetSymbolAddress((void**)&p_y,  g_y);
    cudaGetSymbolAddress((void**)&p_r,  g_r);
    cudaGetSymbolAddress((void**)&p_wd, g_wd);
    cudaGetSymbolAddress((void**)&p_z,  g_z);
    cudaGetSymbolAddress((void**)&p_s1, g_s1);
    cudaGetSymbolAddress((void**)&p_h1, g_h1);
    cudaGetSymbolAddress((void**)&p_sr, g_sr);
    cudaGetSymbolAddress((void**)&p_hr, g_hr);
    cudaGetSymbolAddress((void**)&p_s3, g_s3);
    cudaGetSymbolAddress((void**)&p_h3, g_h3);

    precompute_kernel<<<1, 256>>>(b1, bn1_g, bn1_b, bn1_m, bn1_v,
                                  red_b, rbn_g, rbn_b, rbn_m, rbn_v,
                                  bn2_g, bn2_b, bn2_m, bn2_v,
                                  b3, bn3_g, bn3_b, bn3_m, bn3_v);

    const int NT = (HW + BN - 1) / BN;  // 25

    // y = tanh(bn1(W1 @ x))
    gemm_epi<0><<<dim3(NT, CC / BM, BB), 256>>>(
        w1, x, p_y, p_s1, p_h1, nullptr,
        CC, HW, CC, (long)CC * HW, (long)CC * HW, 0);

    // r = relu(bn_red(RedW @ y))
    gemm_epi<1><<<dim3(NT, RED / BM, BB), 256>>>(
        red_w, p_y, p_r, p_sr, p_hr, nullptr,
        RED, HW, CC, (long)CC * HW, (long)RED * HW, 0);

    // wd = SpanW @ r + span_b
    gemm_epi<2><<<dim3(NT, (KKG + BM - 1) / BM, BB), 256>>>(
        span_w, p_r, p_wd, nullptr, span_b, nullptr,
        KKG, HW, RED, (long)RED * HW, (long)KKG * HW, 0);

    // z = tanh(bn2(involution(y, wd)))
    involution_kernel<<<dim3(WW / TW, HH / TH, BB * GG), dim3(TW, TH)>>>();

    // out = bn3(W3 @ z) + x
    gemm_epi<3><<<dim3(NT, CC / BM, BB), 256>>>(
        w3, p_z, out, p_s3, p_h3, x,
        CC, HW, CC, (long)CC * HW, (long)CC * HW, (long)CC * HW);
}

// round 3
// speedup vs baseline: 1.3029x; 1.3029x over previous
#include <cuda_runtime.h>
#include <cuda_bf16.h>
#include <math.h>

// ---------------------------------------------------------------------------
// Problem constants
// ---------------------------------------------------------------------------
#define BB   16
#define CC   256
#define HH   56
#define WW   56
#define HW   (HH*WW)          // 3136
#define KK   7
#define GCC  16
#define GG   16               // groups
#define RED  64
#define KKG  (KK*KK*GG)       // 784
#define PADI 3

// ---------------------------------------------------------------------------
// Scratch (device globals; no allocation allowed)
// ---------------------------------------------------------------------------
__device__ float g_y [BB*CC*HW];     // 51.4 MB  tanh(bn1(conv1))
__device__ float g_r [BB*RED*HW];    // 12.8 MB  relu(bn_red(red conv))
__device__ float g_wd[BB*KKG*HW];    // 157 MB   span conv output (dyn kernels)
__device__ float g_z [BB*CC*HW];     // 51.4 MB  tanh(bn2(involution))

__device__ float g_s1[CC], g_h1[CC];
__device__ float g_sr[RED], g_hr[RED];
__device__ float g_s2[CC], g_h2[CC];
__device__ float g_s3[CC], g_h3[CC];

// ---------------------------------------------------------------------------
// Fold BN (+conv bias) into per-channel scale/shift
// ---------------------------------------------------------------------------
__global__ void precompute_kernel(
    const float* __restrict__ b1,
    const float* __restrict__ g1, const float* __restrict__ be1,
    const float* __restrict__ m1, const float* __restrict__ v1,
    const float* __restrict__ redb,
    const float* __restrict__ rg, const float* __restrict__ rb,
    const float* __restrict__ rm, const float* __restrict__ rv,
    const float* __restrict__ g2, const float* __restrict__ be2,
    const float* __restrict__ m2, const float* __restrict__ v2,
    const float* __restrict__ b3,
    const float* __restrict__ g3, const float* __restrict__ be3,
    const float* __restrict__ m3, const float* __restrict__ v3)
{
    int c = threadIdx.x;
    if (c < CC) {
        float s = g1[c] * rsqrtf(v1[c] + 1e-5f);
        g_s1[c] = s; g_h1[c] = b1[c]*s + be1[c] - m1[c]*s;
        s = g2[c] * rsqrtf(v2[c] + 1e-5f);
        g_s2[c] = s; g_h2[c] = be2[c] - m2[c]*s;          // no conv bias here
        s = g3[c] * rsqrtf(v3[c] + 1e-5f);
        g_s3[c] = s; g_h3[c] = b3[c]*s + be3[c] - m3[c]*s;
    }
    if (c < RED) {
        float s = rg[c] * rsqrtf(rv[c] + 1e-5f);
        g_sr[c] = s; g_hr[c] = redb[c]*s + rb[c] - rm[c]*s;
    }
}

// ---------------------------------------------------------------------------
// Double-buffered SGEMM:  C[b][m][n] = sum_k A[m][k] * B[b][k][n]
// Block tile 128x128, K-tile 16, 256 threads, 8x8 per-thread fragments.
//   EPI 0: tanh(v*scale+shift)    EPI 1: relu(v*scale+shift)
//   EPI 2: v+shift                EPI 3: v*scale+shift + resid
// ---------------------------------------------------------------------------
#define BM 128
#define BN 128
#define BKT 16
#define BMP 132   // padded As row to de-conflict stores

template<int EPI>
__global__ __launch_bounds__(256, 2)
void gemm_epi(const float* __restrict__ A, const float* __restrict__ Bm,
              float* __restrict__ Cm,
              const float* __restrict__ scale, const float* __restrict__ shift,
              const float* __restrict__ resid,
              int M, int N, int K, long strideB, long strideC, long strideR)
{
    const int b  = blockIdx.z;
    const float* Bp = Bm + (long)b * strideB;
    float*       Cp = Cm + (long)b * strideC;
    const float* Rp = (EPI == 3) ? resid + (long)b * strideR : nullptr;

    const int m0 = blockIdx.y * BM;
    const int n0 = blockIdx.x * BN;
    const int tid = threadIdx.x;
    const int tx = tid & 15;        // 0..15 -> n frag
    const int ty = tid >> 4;        // 0..15 -> m frag

    __shared__ float As[2][BKT][BMP];
    __shared__ float Bs[2][BKT][BN];

    // load indices: A tile is BM x BKT (2 float4/thread), B tile BKT x BN
    const int arow = tid >> 2;            // 0..63  (+64 for p=1)
    const int acol = (tid & 3) << 2;      // 0,4,8,12
    const int brow = tid >> 5;            // 0..7   (+8 for p=1)
    const int bcol = (tid & 31) << 2;     // 0..124

    float acc[8][8];
    #pragma unroll
    for (int i = 0; i < 8; i++)
        #pragma unroll
        for (int j = 0; j < 8; j++) acc[i][j] = 0.f;

    float4 ra[2], rb[2];
    const float4 z4 = make_float4(0.f, 0.f, 0.f, 0.f);

    const int gnb = n0 + bcol;
    const bool bok = (gnb < N);           // N%4==0 so whole float4 valid

    // ---- global load for k-tile kt into registers ----
    auto loadG = [&](int kt) {
        #pragma unroll
        for (int p = 0; p < 2; p++) {
            int gm = m0 + arow + p * 64;
            ra[p] = (gm < M) ? *reinterpret_cast<const float4*>(&A[(long)gm * K + kt + acol]) : z4;
            int gk = kt + brow + p * 8;
            rb[p] = bok ? *reinterpret_cast<const float4*>(&Bp[(long)gk * N + gnb]) : z4;
        }
    };
    // ---- registers -> smem buffer ----
    auto storeS = [&](int buf) {
        #pragma unroll
        for (int p = 0; p < 2; p++) {
            int r = arow + p * 64;
            As[buf][acol + 0][r] = ra[p].x;
            As[buf][acol + 1][r] = ra[p].y;
            As[buf][acol + 2][r] = ra[p].z;
            As[buf][acol + 3][r] = ra[p].w;
            *reinterpret_cast<float4*>(&Bs[buf][brow + p * 8][bcol]) = rb[p];
        }
    };

    loadG(0);
    storeS(0);
    __syncthreads();

    const int nk = K / BKT;
    for (int t = 0; t < nk; t++) {
        int cur = t & 1;
        if (t + 1 < nk) loadG((t + 1) * BKT);

        #pragma unroll
        for (int k = 0; k < BKT; k++) {
            float a[8], bv[8];
            *reinterpret_cast<float4*>(a)      = *reinterpret_cast<const float4*>(&As[cur][k][ty * 8]);
            *reinterpret_cast<float4*>(a + 4)  = *reinterpret_cast<const float4*>(&As[cur][k][ty * 8 + 4]);
            *reinterpret_cast<float4*>(bv)     = *reinterpret_cast<const float4*>(&Bs[cur][k][tx * 8]);
            *reinterpret_cast<float4*>(bv + 4) = *reinterpret_cast<const float4*>(&Bs[cur][k][tx * 8 + 4]);
            #pragma unroll
            for (int i = 0; i < 8; i++)
                #pragma unroll
                for (int j = 0; j < 8; j++)
                    acc[i][j] = fmaf(a[i], bv[j], acc[i][j]);
        }

        if (t + 1 < nk) storeS(cur ^ 1);
        __syncthreads();
    }

    // ---- epilogue ----
    #pragma unroll
    for (int i = 0; i < 8; i++) {
        int gm = m0 + ty * 8 + i;
        if (gm >= M) continue;
        float sc = 1.f, sh;
        if (EPI == 2) { sh = shift[gm]; }
        else          { sc = scale[gm]; sh = shift[gm]; }
        #pragma unroll
        for (int jj = 0; jj < 2; jj++) {
            int gn = n0 + tx * 8 + jj * 4;
            if (gn >= N) continue;
            float4 v;
            v.x = acc[i][jj * 4 + 0];
            v.y = acc[i][jj * 4 + 1];
            v.z = acc[i][jj * 4 + 2];
            v.w = acc[i][jj * 4 + 3];
            if (EPI == 0) {
                v.x = tanhf(fmaf(v.x, sc, sh)); v.y = tanhf(fmaf(v.y, sc, sh));
                v.z = tanhf(fmaf(v.z, sc, sh)); v.w = tanhf(fmaf(v.w, sc, sh));
            } else if (EPI == 1) {
                v.x = fmaxf(fmaf(v.x, sc, sh), 0.f); v.y = fmaxf(fmaf(v.y, sc, sh), 0.f);
                v.z = fmaxf(fmaf(v.z, sc, sh), 0.f); v.w = fmaxf(fmaf(v.w, sc, sh), 0.f);
            } else if (EPI == 2) {
                v.x += sh; v.y += sh; v.z += sh; v.w += sh;
            } else {
                float4 r = *reinterpret_cast<const float4*>(&Rp[(long)gm * N + gn]);
                v.x = fmaf(v.x, sc, sh) + r.x; v.y = fmaf(v.y, sc, sh) + r.y;
                v.z = fmaf(v.z, sc, sh) + r.z; v.w = fmaf(v.w, sc, sh) + r.w;
            }
            *reinterpret_cast<float4*>(&Cp[(long)gm * N + gn]) = v;
        }
    }
}

// ---------------------------------------------------------------------------
// Involution + bn2 + tanh, fused.
// Block: one (batch, group), spatial tile 28x8. 16 group-channels in regs.
// ---------------------------------------------------------------------------
#define TW 28
#define TH 8

__global__ __launch_bounds__(224)
void involution_kernel()
{
    const int bg = blockIdx.z;
    const int b  = bg >> 4;
    const int g  = bg & 15;
    const int h0 = blockIdx.y * TH;
    const int w0 = blockIdx.x * TW;
    const int tid = threadIdx.y * TW + threadIdx.x;

    __shared__ float ys[GCC][TH + 6][TW + 6];   // 16 x 14 x 34 = 30.4 KB

    const float* ybase = g_y + ((long)(b * CC + g * GCC)) * HW;
    const int TOT = GCC * (TH + 6) * (TW + 6);  // 7616
    for (int idx = tid; idx < TOT; idx += TW * TH) {
        int gc  = idx / ((TH + 6) * (TW + 6));
        int rem = idx % ((TH + 6) * (TW + 6));
        int lh  = rem / (TW + 6);
        int lw  = rem % (TW + 6);
        int gh = h0 + lh - PADI;
        int gw = w0 + lw - PADI;
        float v = 0.f;
        if (gh >= 0 && gh < HH && gw >= 0 && gw < WW)
            v = ybase[(long)gc * HW + gh * WW + gw];
        ys[gc][lh][lw] = v;
    }
    __syncthreads();

    const int h = h0 + threadIdx.y;
    const int w = w0 + threadIdx.x;
    const float* wdp = g_wd + ((long)b * KKG + g * (KK * KK)) * HW + h * WW + w;

    float acc[GCC];
    #pragma unroll
    for (int gc = 0; gc < GCC; gc++) acc[gc] = 0.f;

    #pragma unroll
    for (int i = 0; i < KK; i++) {
        #pragma unroll
        for (int j = 0; j < KK; j++) {
            float wv = wdp[(long)(i * KK + j) * HW];
            #pragma unroll
            for (int gc = 0; gc < GCC; gc++)
                acc[gc] = fmaf(wv, ys[gc][threadIdx.y + i][threadIdx.x + j], acc[gc]);
        }
    }

    long zbase = ((long)(b * CC + g * GCC)) * HW + h * WW + w;
    #pragma unroll
    for (int gc = 0; gc < GCC; gc++) {
        int c = g * GCC + gc;
        g_z[zbase + (long)gc * HW] = tanhf(fmaf(acc[gc], g_s2[c], g_h2[c]));
    }
}

// ---------------------------------------------------------------------------
// Host
// ---------------------------------------------------------------------------
extern "C" void kernel_launch(void* const* d_in, const int* in_sizes, int n_in,
                              void* d_out, int out_size)
{
    const float* x     = (const float*)d_in[0];
    const float* w1    = (const float*)d_in[1];
    const float* b1    = (const float*)d_in[2];
    const float* bn1_g = (const float*)d_in[3];
    const float* bn1_b = (const float*)d_in[4];
    const float* bn1_m = (const float*)d_in[5];
    const float* bn1_v = (const float*)d_in[6];
    const float* red_w = (const float*)d_in[7];
    const float* red_b = (const float*)d_in[8];
    const float* rbn_g = (const float*)d_in[9];
    const float* rbn_b = (const float*)d_in[10];
    const float* rbn_m = (const float*)d_in[11];
    const float* rbn_v = (const float*)d_in[12];
    const float* span_w= (const float*)d_in[13];
    const float* span_b= (const float*)d_in[14];
    const float* bn2_g = (const float*)d_in[15];
    const float* bn2_b = (const float*)d_in[16];
    const float* bn2_m = (const float*)d_in[17];
    const float* bn2_v = (const float*)d_in[18];
    const float* w3    = (const float*)d_in[19];
    const float* b3    = (const float*)d_in[20];
    const float* bn3_g = (const float*)d_in[21];
    const float* bn3_b = (const float*)d_in[22];
    const float* bn3_m = (const float*)d_in[23];
    const float* bn3_v = (const float*)d_in[24];
    float* out = (float*)d_out;

    float *p_y, *p_r, *p_wd, *p_z;
    float *p_s1, *p_h1, *p_sr, *p_hr, *p_s3, *p_h3;
    cudaGetSymbolAddress((void**)&p_y,  g_y);
    cudaGetSymbolAddress((void**)&p_r,  g_r);
    cudaGetSymbolAddress((void**)&p_wd, g_wd);
    cudaGetSymbolAddress((void**)&p_z,  g_z);
    cudaGetSymbolAddress((void**)&p_s1, g_s1);
    cudaGetSymbolAddress((void**)&p_h1, g_h1);
    cudaGetSymbolAddress((void**)&p_sr, g_sr);
    cudaGetSymbolAddress((void**)&p_hr, g_hr);
    cudaGetSymbolAddress((void**)&p_s3, g_s3);
    cudaGetSymbolAddress((void**)&p_h3, g_h3);

    precompute_kernel<<<1, 256>>>(b1, bn1_g, bn1_b, bn1_m, bn1_v,
                                  red_b, rbn_g, rbn_b, rbn_m, rbn_v,
                                  bn2_g, bn2_b, bn2_m, bn2_v,
                                  b3, bn3_g, bn3_b, bn3_m, bn3_v);

    const int NT = (HW + BN - 1) / BN;  // 25

    // y = tanh(bn1(W1 @ x))
    gemm_epi<0><<<dim3(NT, (CC + BM - 1) / BM, BB), 256>>>(
        w1, x, p_y, p_s1, p_h1, nullptr,
        CC, HW, CC, (long)CC * HW, (long)CC * HW, 0);

    // r = relu(bn_red(RedW @ y))
    gemm_epi<1><<<dim3(NT, (RED + BM - 1) / BM, BB), 256>>>(
        red_w, p_y, p_r, p_sr, p_hr, nullptr,
        RED, HW, CC, (long)CC * HW, (long)RED * HW, 0);

    // wd = SpanW @ r + span_b
    gemm_epi<2><<<dim3(NT, (KKG + BM - 1) / BM, BB), 256>>>(
        span_w, p_r, p_wd, nullptr, span_b, nullptr,
        KKG, HW, RED, (long)RED * HW, (long)KKG * HW, 0);

    // z = tanh(bn2(involution(y, wd)))
    involution_kernel<<<dim3(WW / TW, HH / TH, BB * GG), dim3(TW, TH)>>>();

    // out = bn3(W3 @ z) + x
    gemm_epi<3><<<dim3(NT, (CC + BM - 1) / BM, BB), 256>>>(
        w3, p_z, out, p_s3, p_h3, x,
        CC, HW, CC, (long)CC * HW, (long)CC * HW, (long)CC * HW);
}

// round 5
// speedup vs baseline: 1.5415x; 1.1832x over previous
#include <cuda_runtime.h>
#include <cuda_bf16.h>
#include <math.h>
#include <stdint.h>

// ---------------------------------------------------------------------------
// Problem constants
// ---------------------------------------------------------------------------
#define BB   16
#define CC   256
#define HH   56
#define WW   56
#define HW   3136
#define HWP  3200            // pixel dim padded to multiple of 128
#define KK   7
#define GCC  16
#define GG   16
#define RED  64
#define KKG  784
#define PADI 3

// ---------------------------------------------------------------------------
// Scratch (device globals; zero-initialized; no allocation allowed)
// Activations live pixel-major: [b][px][ch], split into bf16 hi + lo.
// ---------------------------------------------------------------------------
__device__ __align__(16) __nv_bfloat16 g_xh[BB*HWP*CC], g_xl[BB*HWP*CC];
__device__ __align__(16) __nv_bfloat16 g_yh[BB*HWP*CC], g_yl[BB*HWP*CC];
__device__ __align__(16) __nv_bfloat16 g_rh[BB*HWP*RED], g_rl[BB*HWP*RED];
__device__ __align__(16) __nv_bfloat16 g_zh[BB*HWP*CC], g_zl[BB*HWP*CC];
__device__ __align__(16) float g_wd[(size_t)BB*HWP*KKG];      // [b][px][784] fp32

// weights split to bf16 hi/lo (M padded to 128-multiples, padded rows zero)
__device__ __align__(16) __nv_bfloat16 g_w1h[CC*CC],  g_w1l[CC*CC];
__device__ __align__(16) __nv_bfloat16 g_w3h[CC*CC],  g_w3l[CC*CC];
__device__ __align__(16) __nv_bfloat16 g_rwh[128*CC], g_rwl[128*CC];
__device__ __align__(16) __nv_bfloat16 g_swh[896*RED], g_swl[896*RED];

__device__ float g_s1[CC], g_h1[CC];
__device__ float g_sr[RED], g_hr[RED];
__device__ float g_s2[CC], g_h2[CC];
__device__ float g_s3[CC], g_h3[CC];

// ---------------------------------------------------------------------------
// PTX helpers (sm_80-era instructions only: valid on plain sm_103 target)
// ---------------------------------------------------------------------------
__device__ __forceinline__ uint32_t s2u(const void* p) {
    uint32_t a;
    asm("{ .reg .u64 t; cvta.to.shared.u64 t, %1; cvt.u32.u64 %0, t; }" : "=r"(a) : "l"(p));
    return a;
}

__device__ __forceinline__ void cpasync16(uint32_t saddr, const void* g) {
    asm volatile("cp.async.cg.shared.global [%0], [%1], 16;" :: "r"(saddr), "l"(g));
}

__device__ __forceinline__ void ldsm4(uint32_t* r, uint32_t a) {
    asm volatile("ldmatrix.sync.aligned.m8n8.x4.shared.b16 {%0,%1,%2,%3}, [%4];"
                 : "=r"(r[0]), "=r"(r[1]), "=r"(r[2]), "=r"(r[3]) : "r"(a));
}

__device__ __forceinline__ void mma_bf16(float* c, const uint32_t* a, const uint32_t* b) {
    asm volatile("mma.sync.aligned.m16n8k16.row.col.f32.bf16.bf16.f32 "
        "{%0,%1,%2,%3}, {%4,%5,%6,%7}, {%8,%9}, {%0,%1,%2,%3};"
        : "+f"(c[0]), "+f"(c[1]), "+f"(c[2]), "+f"(c[3])
        : "r"(a[0]), "r"(a[1]), "r"(a[2]), "r"(a[3]), "r"(b[0]), "r"(b[1]));
}

__device__ __forceinline__ void split2(float v, __nv_bfloat16& h, __nv_bfloat16& l) {
    h = __float2bfloat16_rn(v);
    l = __float2bfloat16_rn(v - __bfloat162float(h));
}

// SW64-style swizzle for 64-byte rows: conflict-free cp.async stores + ldmatrix
__device__ __forceinline__ uint32_t soff(int r, int c16) {
    return (uint32_t)(r * 64) + (uint32_t)(((c16 ^ ((r >> 1) & 3)) & 3) << 4);
}

// ---------------------------------------------------------------------------
// Fold BN (+conv bias) into per-channel scale/shift
// ---------------------------------------------------------------------------
__global__ void precompute_kernel(
    const float* __restrict__ b1,
    const float* __restrict__ g1, const float* __restrict__ be1,
    const float* __restrict__ m1, const float* __restrict__ v1,
    const float* __restrict__ redb,
    const float* __restrict__ rg, const float* __restrict__ rb,
    const float* __restrict__ rm, const float* __restrict__ rv,
    const float* __restrict__ g2, const float* __restrict__ be2,
    const float* __restrict__ m2, const float* __restrict__ v2,
    const float* __restrict__ b3,
    const float* __restrict__ g3, const float* __restrict__ be3,
    const float* __restrict__ m3, const float* __restrict__ v3)
{
    int c = threadIdx.x;
    if (c < CC) {
        float s = g1[c] * rsqrtf(v1[c] + 1e-5f);
        g_s1[c] = s; g_h1[c] = b1[c]*s + be1[c] - m1[c]*s;
        s = g2[c] * rsqrtf(v2[c] + 1e-5f);
        g_s2[c] = s; g_h2[c] = be2[c] - m2[c]*s;
        s = g3[c] * rsqrtf(v3[c] + 1e-5f);
        g_s3[c] = s; g_h3[c] = b3[c]*s + be3[c] - m3[c]*s;
    }
    if (c < RED) {
        float s = rg[c] * rsqrtf(rv[c] + 1e-5f);
        g_sr[c] = s; g_hr[c] = redb[c]*s + rb[c] - rm[c]*s;
    }
}

// ---------------------------------------------------------------------------
// Split weights into bf16 hi/lo (zero padding of M to 128-multiples)
// ---------------------------------------------------------------------------
__global__ void prep_weights(const float* __restrict__ w1, const float* __restrict__ w3,
                             const float* __restrict__ redw, const float* __restrict__ spanw)
{
    int i = blockIdx.x * 256 + threadIdx.x;   // 65536 threads
    if (i < CC * CC) {
        split2(w1[i], g_w1h[i], g_w1l[i]);
        split2(w3[i], g_w3h[i], g_w3l[i]);
    }
    if (i < 128 * CC) {
        int r = i >> 8;
        float v = (r < RED) ? redw[i] : 0.f;
        split2(v, g_rwh[i], g_rwl[i]);
    }
    if (i < 896 * RED) {
        int r = i / RED;
        float v = (r < KKG) ? spanw[i] : 0.f;
        split2(v, g_swh[i], g_swl[i]);
    }
}

// ---------------------------------------------------------------------------
// Transpose + split input x: [b][c][px] fp32 -> [b][px][c] bf16 hi/lo
// ---------------------------------------------------------------------------
__global__ void convert_x_kernel(const float* __restrict__ x)
{
    __shared__ float t[32][33];
    const int b = blockIdx.z, px0 = blockIdx.x * 32, c0 = blockIdx.y * 32;
    #pragma unroll
    for (int i = 0; i < 4; i++) {
        int cy = threadIdx.y + i * 8;
        t[cy][threadIdx.x] = x[((long)(b * CC + c0 + cy)) * HW + px0 + threadIdx.x];
    }
    __syncthreads();
    #pragma unroll
    for (int i = 0; i < 4; i++) {
        int py = threadIdx.y + i * 8;
        float v = t[threadIdx.x][py];
        long a = ((long)b * HWP + px0 + py) * CC + c0 + threadIdx.x;
        __nv_bfloat16 hi, lo; split2(v, hi, lo);
        g_xh[a] = hi; g_xl[a] = lo;
    }
}

// ---------------------------------------------------------------------------
// bf16-split GEMM on mma.sync (HMMA): D[m, px] = sum_k A[m,k] * B[px,k]
//   D ~= Ah*Bh + Ah*Bl + Al*Bh  (fp32 accum)
// Block 128x128, 8 warps (64x32 warp tiles), K-chunk 32, 3-stage cp.async.
// EPI 0: tanh(v*sc+sh)->bf16 pair   EPI 1: relu->bf16 pair
// EPI 2: v+shift -> fp32 wd         EPI 3: v*sc+sh + resid -> fp32 NCHW
// ---------------------------------------------------------------------------
#define KC      32
#define ARR_B   8192              // 128 rows x 64B
#define STAGE_B (4*ARR_B)         // Ah, Al, Bh, Bl
#define NSTG    3
#define SMEM_SZ (NSTG*STAGE_B)    // 98304

template<int EPI>
__global__ __launch_bounds__(256, 2)
void gemm_tc(const __nv_bfloat16* __restrict__ Ah, const __nv_bfloat16* __restrict__ Al,
             const __nv_bfloat16* __restrict__ Bh, const __nv_bfloat16* __restrict__ Bl,
             int Ka, int Mvalid, int Cs,
             float* __restrict__ outF,
             __nv_bfloat16* __restrict__ Oh, __nv_bfloat16* __restrict__ Ol,
             const float* __restrict__ scale, const float* __restrict__ shift,
             const float* __restrict__ resid)
{
    extern __shared__ char smem[];
    const int tid = threadIdx.x, wid = tid >> 5, lane = tid & 31;
    const int b = blockIdx.z, m0 = blockIdx.y << 7, px0 = blockIdx.x << 7;
    const uint32_t sb = s2u(smem);

    const int wm = (wid & 1) * 64;        // warp m offset in block tile
    const int wn = (wid >> 1) * 32;       // warp n (pixel) offset

    // cp.async loader mapping: 2 rows per thread per array, 16B each
    const int lr = tid >> 2;              // 0..63
    const int lc = tid & 3;               // 16B chunk within 64B row
    const long bbase = (long)b * HWP + px0;

    float acc[4][4][4];
    #pragma unroll
    for (int i = 0; i < 4; i++)
        #pragma unroll
        for (int j = 0; j < 4; j++)
            #pragma unroll
            for (int q = 0; q < 4; q++) acc[i][j][q] = 0.f;

    auto issue = [&](int kt, int s) {
        const int k0 = kt * KC;
        const uint32_t sbase = sb + s * STAGE_B;
        #pragma unroll
        for (int p = 0; p < 2; p++) {
            int r = lr + p * 64;
            uint32_t o = soff(r, lc);
            long ai = (long)(m0 + r) * Ka + k0 + lc * 8;
            long bi = (bbase + r) * Ka + k0 + lc * 8;
            cpasync16(sbase + o,             Ah + ai);
            cpasync16(sbase + ARR_B + o,     Al + ai);
            cpasync16(sbase + 2 * ARR_B + o, Bh + bi);
            cpasync16(sbase + 3 * ARR_B + o, Bl + bi);
        }
        asm volatile("cp.async.commit_group;" ::: "memory");
    };

    const int nk = Ka / KC;
    #pragma unroll
    for (int s = 0; s < NSTG; s++) if (s < nk) issue(s, s);

    for (int t = 0; t < nk; t++) {
        const int rem = nk - 1 - t;
        if (rem >= 2)      asm volatile("cp.async.wait_group 2;" ::: "memory");
        else if (rem == 1) asm volatile("cp.async.wait_group 1;" ::: "memory");
        else               asm volatile("cp.async.wait_group 0;" ::: "memory");
        __syncthreads();

        const uint32_t sbase = sb + (t % 3) * STAGE_B;
        #pragma unroll
        for (int kb = 0; kb < 2; kb++) {
            // B fragments: 2 ldmatrix.x4 per operand cover 4 n8-tiles
            uint32_t bh[2][4], bl[2][4];
            #pragma unroll
            for (int pr = 0; pr < 2; pr++) {
                int n = wn + pr * 16 + (lane & 7) + ((lane >> 4) << 3);
                int c = kb * 2 + ((lane >> 3) & 1);
                uint32_t o = soff(n, c);
                ldsm4(bh[pr], sbase + 2 * ARR_B + o);
                ldsm4(bl[pr], sbase + 3 * ARR_B + o);
            }
            #pragma unroll
            for (int mi = 0; mi < 4; mi++) {
                int r = wm + mi * 16 + (lane & 15);
                int c = kb * 2 + (lane >> 4);
                uint32_t o = soff(r, c);
                uint32_t ah[4], al[4];
                ldsm4(ah, sbase + o);
                ldsm4(al, sbase + ARR_B + o);
                #pragma unroll
                for (int nt = 0; nt < 4; nt++) {
                    const uint32_t* ph = &bh[nt >> 1][(nt & 1) * 2];
                    const uint32_t* pl = &bl[nt >> 1][(nt & 1) * 2];
                    mma_bf16(acc[mi][nt], ah, ph);
                    mma_bf16(acc[mi][nt], ah, pl);
                    mma_bf16(acc[mi][nt], al, ph);
                }
            }
        }
        __syncthreads();
        if (t + NSTG < nk) issue(t + NSTG, t % 3);
    }

    // ---- epilogue straight from registers ----
    const int g = lane >> 2, tg = lane & 3;
    const long pbase = (long)b * HWP;

    #pragma unroll
    for (int mi = 0; mi < 4; mi++) {
        const int mA = m0 + wm + mi * 16 + g;
        const int mB = mA + 8;
        const bool okA = (mA < Mvalid), okB = (mB < Mvalid);
        float scA = 0.f, shA = 0.f, scB = 0.f, shB = 0.f;
        if (EPI == 2) {
            if (okA) shA = shift[mA];
            if (okB) shB = shift[mB];
        } else {
            if (okA) { scA = scale[mA]; shA = shift[mA]; }
            if (okB) { scB = scale[mB]; shB = shift[mB]; }
        }
        #pragma unroll
        for (int nt = 0; nt < 4; nt++) {
            const int px = px0 + wn + nt * 8 + tg * 2;
            const float* a4 = acc[mi][nt];
            if (EPI == 0 || EPI == 1) {
                if (okA) {
                    long ad = (pbase + px) * Cs + mA;
                    float v0 = fmaf(a4[0], scA, shA), v1 = fmaf(a4[1], scA, shA);
                    if (EPI == 0) { v0 = tanhf(v0); v1 = tanhf(v1); }
                    else          { v0 = fmaxf(v0, 0.f); v1 = fmaxf(v1, 0.f); }
                    __nv_bfloat16 h0, l0, h1, l1;
                    split2(v0, h0, l0); split2(v1, h1, l1);
                    Oh[ad] = h0; Ol[ad] = l0; Oh[ad + Cs] = h1; Ol[ad + Cs] = l1;
                }
                if (okB) {
                    long ad = (pbase + px) * Cs + mB;
                    float v0 = fmaf(a4[2], scB, shB), v1 = fmaf(a4[3], scB, shB);
                    if (EPI == 0) { v0 = tanhf(v0); v1 = tanhf(v1); }
                    else          { v0 = fmaxf(v0, 0.f); v1 = fmaxf(v1, 0.f); }
                    __nv_bfloat16 h0, l0, h1, l1;
                    split2(v0, h0, l0); split2(v1, h1, l1);
                    Oh[ad] = h0; Ol[ad] = l0; Oh[ad + Cs] = h1; Ol[ad + Cs] = l1;
                }
            } else if (EPI == 2) {
                long a0 = (pbase + px) * (long)KKG;
                if (okA) { outF[a0 + mA] = a4[0] + shA; outF[a0 + KKG + mA] = a4[1] + shA; }
                if (okB) { outF[a0 + mB] = a4[2] + shB; outF[a0 + KKG + mB] = a4[3] + shB; }
            } else {
                if (px < HW) {
                    long aA = (long)(b * CC + mA) * HW + px;
                    long aB = (long)(b * CC + mB) * HW + px;
                    outF[aA]     = fmaf(a4[0], scA, shA) + resid[aA];
                    outF[aA + 1] = fmaf(a4[1], scA, shA) + resid[aA + 1];
                    outF[aB]     = fmaf(a4[2], scB, shB) + resid[aB];
                    outF[aB + 1] = fmaf(a4[3], scB, shB) + resid[aB + 1];
                }
            }
        }
    }
}

// ---------------------------------------------------------------------------
// Involution + bn2 + tanh. y from bf16 hi/lo [px][ch]; wd from [px][784];
// writes z as bf16 hi/lo [px][ch].
// ---------------------------------------------------------------------------
__global__ __launch_bounds__(224)
void involution_kernel()
{
    const int bg = blockIdx.z;
    const int b = bg >> 4, g = bg & 15;
    const int h0 = blockIdx.y * 8, w0 = blockIdx.x * 28;
    const int tid = threadIdx.y * 28 + threadIdx.x;

    __shared__ float ys[GCC][14][34];

    const long ybase = (long)b * HWP * CC + g * GCC;
    for (int idx = tid; idx < 14 * 34; idx += 224) {
        int lh = idx / 34, lw = idx - lh * 34;
        int gh = h0 + lh - PADI, gw = w0 + lw - PADI;
        if (gh >= 0 && gh < HH && gw >= 0 && gw < WW) {
            long a = ybase + (long)(gh * WW + gw) * CC;
            union { uint4 u[2]; __nv_bfloat16 h[16]; } uh, ul;
            uh.u[0] = *(const uint4*)(g_yh + a);
            uh.u[1] = *(const uint4*)(g_yh + a + 8);
            ul.u[0] = *(const uint4*)(g_yl + a);
            ul.u[1] = *(const uint4*)(g_yl + a + 8);
            #pragma unroll
            for (int j = 0; j < 16; j++)
                ys[j][lh][lw] = __bfloat162float(uh.h[j]) + __bfloat162float(ul.h[j]);
        } else {
            #pragma unroll
            for (int j = 0; j < 16; j++) ys[j][lh][lw] = 0.f;
        }
    }
    __syncthreads();

    const int h = h0 + threadIdx.y, w = w0 + threadIdx.x;
    const long px = (long)b * HWP + h * WW + w;
    const float* wdp = g_wd + px * KKG + g * (KK * KK);

    float acc[GCC];
    #pragma unroll
    for (int q = 0; q < GCC; q++) acc[q] = 0.f;

    #pragma unroll
    for (int i = 0; i < KK; i++) {
        #pragma unroll
        for (int j = 0; j < KK; j++) {
            float wv = wdp[i * KK + j];
            #pragma unroll
            for (int q = 0; q < GCC; q++)
                acc[q] = fmaf(wv, ys[q][threadIdx.y + i][threadIdx.x + j], acc[q]);
        }
    }

    long za = px * CC + g * GCC;
    union { uint4 u[2]; __nv_bfloat16 hv[16]; } oh, ol;
    #pragma unroll
    for (int q = 0; q < GCC; q++) {
        int c = g * GCC + q;
        float v = tanhf(fmaf(acc[q], g_s2[c], g_h2[c]));
        __nv_bfloat16 hi, lo; split2(v, hi, lo);
        oh.hv[q] = hi; ol.hv[q] = lo;
    }
    *(uint4*)(g_zh + za)     = oh.u[0];
    *(uint4*)(g_zh + za + 8) = oh.u[1];
    *(uint4*)(g_zl + za)     = ol.u[0];
    *(uint4*)(g_zl + za + 8) = ol.u[1];
}

// ---------------------------------------------------------------------------
// Host
// ---------------------------------------------------------------------------
extern "C" void kernel_launch(void* const* d_in, const int* in_sizes, int n_in,
                              void* d_out, int out_size)
{
    const float* x     = (const float*)d_in[0];
    const float* w1    = (const float*)d_in[1];
    const float* b1    = (const float*)d_in[2];
    const float* bn1_g = (const float*)d_in[3];
    const float* bn1_b = (const float*)d_in[4];
    const float* bn1_m = (const float*)d_in[5];
    const float* bn1_v = (const float*)d_in[6];
    const float* red_w = (const float*)d_in[7];
    const float* red_b = (const float*)d_in[8];
    const float* rbn_g = (const float*)d_in[9];
    const float* rbn_b = (const float*)d_in[10];
    const float* rbn_m = (const float*)d_in[11];
    const float* rbn_v = (const float*)d_in[12];
    const float* span_w= (const float*)d_in[13];
    const float* span_b= (const float*)d_in[14];
    const float* bn2_g = (const float*)d_in[15];
    const float* bn2_b = (const float*)d_in[16];
    const float* bn2_m = (const float*)d_in[17];
    const float* bn2_v = (const float*)d_in[18];
    const float* w3    = (const float*)d_in[19];
    const float* b3    = (const float*)d_in[20];
    const float* bn3_g = (const float*)d_in[21];
    const float* bn3_b = (const float*)d_in[22];
    const float* bn3_m = (const float*)d_in[23];
    const float* bn3_v = (const float*)d_in[24];
    float* out = (float*)d_out;

    __nv_bfloat16 *xh,*xl,*yh,*yl,*rh,*rl,*zh,*zl;
    __nv_bfloat16 *w1h,*w1l,*w3h,*w3l,*rwh,*rwl,*swh,*swl;
    float *wd, *s1,*h1,*sr,*hr,*s3,*h3;
    cudaGetSymbolAddress((void**)&xh, g_xh);  cudaGetSymbolAddress((void**)&xl, g_xl);
    cudaGetSymbolAddress((void**)&yh, g_yh);  cudaGetSymbolAddress((void**)&yl, g_yl);
    cudaGetSymbolAddress((void**)&rh, g_rh);  cudaGetSymbolAddress((void**)&rl, g_rl);
    cudaGetSymbolAddress((void**)&zh, g_zh);  cudaGetSymbolAddress((void**)&zl, g_zl);
    cudaGetSymbolAddress((void**)&w1h, g_w1h); cudaGetSymbolAddress((void**)&w1l, g_w1l);
    cudaGetSymbolAddress((void**)&w3h, g_w3h); cudaGetSymbolAddress((void**)&w3l, g_w3l);
    cudaGetSymbolAddress((void**)&rwh, g_rwh); cudaGetSymbolAddress((void**)&rwl, g_rwl);
    cudaGetSymbolAddress((void**)&swh, g_swh); cudaGetSymbolAddress((void**)&swl, g_swl);
    cudaGetSymbolAddress((void**)&wd, g_wd);
    cudaGetSymbolAddress((void**)&s1, g_s1);  cudaGetSymbolAddress((void**)&h1, g_h1);
    cudaGetSymbolAddress((void**)&sr, g_sr);  cudaGetSymbolAddress((void**)&hr, g_hr);
    cudaGetSymbolAddress((void**)&s3, g_s3);  cudaGetSymbolAddress((void**)&h3, g_h3);

    cudaFuncSetAttribute(gemm_tc<0>, cudaFuncAttributeMaxDynamicSharedMemorySize, SMEM_SZ);
    cudaFuncSetAttribute(gemm_tc<1>, cudaFuncAttributeMaxDynamicSharedMemorySize, SMEM_SZ);
    cudaFuncSetAttribute(gemm_tc<2>, cudaFuncAttributeMaxDynamicSharedMemorySize, SMEM_SZ);
    cudaFuncSetAttribute(gemm_tc<3>, cudaFuncAttributeMaxDynamicSharedMemorySize, SMEM_SZ);

    precompute_kernel<<<1, 256>>>(b1, bn1_g, bn1_b, bn1_m, bn1_v,
                                  red_b, rbn_g, rbn_b, rbn_m, rbn_v,
                                  bn2_g, bn2_b, bn2_m, bn2_v,
                                  b3, bn3_g, bn3_b, bn3_m, bn3_v);
    prep_weights<<<256, 256>>>(w1, w3, red_w, span_w);
    convert_x_kernel<<<dim3(HW/32, CC/32, BB), dim3(32, 8)>>>(x);

    // y = tanh(bn1(W1 @ x))
    gemm_tc<0><<<dim3(HWP/128, 2, BB), 256, SMEM_SZ>>>(
        w1h, w1l, xh, xl, CC, CC, CC, nullptr, yh, yl, s1, h1, nullptr);

    // r = relu(bn_red(RedW @ y))   (M padded 64->128)
    gemm_tc<1><<<dim3(HWP/128, 1, BB), 256, SMEM_SZ>>>(
        rwh, rwl, yh, yl, CC, RED, RED, nullptr, rh, rl, sr, hr, nullptr);

    // wd = SpanW @ r + span_b      (M padded 784->896)
    gemm_tc<2><<<dim3(HWP/128, 7, BB), 256, SMEM_SZ>>>(
        swh, swl, rh, rl, RED, KKG, KKG, wd, nullptr, nullptr, nullptr, span_b, nullptr);

    // z = tanh(bn2(involution(y, wd)))
    involution_kernel<<<dim3(WW/28, HH/8, BB*GG), dim3(28, 8)>>>();

    // out = bn3(W3 @ z) + x
    gemm_tc<3><<<dim3(HWP/128, 2, BB), 256, SMEM_SZ>>>(
        w3h, w3l, zh, zl, CC, CC, CC, out, nullptr, nullptr, s3, h3, x);
}